// round 14
// baseline (speedup 1.0000x reference)
#include <cuda_runtime.h>

// Problem constants (fixed by the dataset)
#define B_COLS   64            // dense columns
#define N_MAX    50048         // neuron count (50000) rounded up
#define NNZ_MAX  800000

// Scratch (no allocation allowed): ping-pong buffers + CSR row pointer
__device__ float g_bufX[N_MAX * B_COLS];
__device__ float g_bufY[N_MAX * B_COLS];
__device__ int   g_row_ptr[N_MAX + 1];

// Software grid-barrier state. count returns to 0 after every barrier;
// gen increases monotonically (+6 per launch) -> deterministic across graph
// replays, no reset kernel needed.
__device__ int g_bar_count = 0;
__device__ int g_bar_gen   = 0;

// ---------------------------------------------------------------------------
// Grid-wide barrier. Safe because the grid is exactly one resident wave
// (1184 blocks x 256 thr @ 32 regs = 2048 thr/SM on 148 SMs; GB300 has 152).
// __threadfence() publishes this block's stores before arrival and
// invalidates this SM's L1 after release (stale-line protection for the
// ping-pong buffers, replacing the per-launch L1 flush).
// ---------------------------------------------------------------------------
__device__ __forceinline__ void grid_barrier(int target, int nblocks) {
    __threadfence();                    // publish stores, order before arrival
    __syncthreads();
    if (threadIdx.x == 0) {
        int arrived = atomicAdd(&g_bar_count, 1);
        if (arrived == nblocks - 1) {
            g_bar_count = 0;            // nobody touches count until release
            __threadfence();
            atomicAdd(&g_bar_gen, 1);   // release
        } else {
            while (*((volatile int*)&g_bar_gen) - target < 0)
                __nanosleep(64);
        }
    }
    __syncthreads();
    __threadfence();                    // invalidate L1 before reading peers' data
}

// ---------------------------------------------------------------------------
// One SpMM phase: out[r,:] = sum_e vals[e] * x[cols[e],:] (+ bias[r]).
// Exactly the proven R7 body (best warm config): one warp per row
// (grid-stride), lane l owns dense cols {2l,2l+1} as float2, vectorized
// uniform metadata, 8 independent 256B gathers in flight, 32-reg footprint.
// ---------------------------------------------------------------------------
__device__ __forceinline__ void spmm_phase(
    const float* __restrict__ vals, const int* __restrict__ cols,
    const int* __restrict__ row_ptr, const float* __restrict__ xin,
    const float* __restrict__ bias, float* __restrict__ out,
    int n, int lane, int warpId, int nWarps, bool has_bias)
{
    const float2* __restrict__ x2 = reinterpret_cast<const float2*>(xin);

    for (int row = warpId; row < n; row += nWarps) {
        int s = row_ptr[row];
        int e = row_ptr[row + 1];

        float accx = 0.0f, accy = 0.0f;

        int k = s;
        // Peel to 4-edge alignment so float4/int4 metadata loads are 16B aligned.
        while (k < e && (k & 3)) {
            float v = vals[k];
            int   c = cols[k];
            float2 a = x2[c * 32 + lane];
            accx = fmaf(v, a.x, accx); accy = fmaf(v, a.y, accy);
            k++;
        }

        // 8 edges/iter: 2 float4 + 2 int4 uniform metadata loads,
        // 8 independent float2 gathers in flight.
        for (; k + 8 <= e; k += 8) {
            float4 v0 = *reinterpret_cast<const float4*>(vals + k);
            float4 v1 = *reinterpret_cast<const float4*>(vals + k + 4);
            int4   c0 = *reinterpret_cast<const int4*>(cols + k);
            int4   c1 = *reinterpret_cast<const int4*>(cols + k + 4);
            float2 a0 = x2[c0.x * 32 + lane];
            float2 a1 = x2[c0.y * 32 + lane];
            float2 a2 = x2[c0.z * 32 + lane];
            float2 a3 = x2[c0.w * 32 + lane];
            float2 a4 = x2[c1.x * 32 + lane];
            float2 a5 = x2[c1.y * 32 + lane];
            float2 a6 = x2[c1.z * 32 + lane];
            float2 a7 = x2[c1.w * 32 + lane];
            accx = fmaf(v0.x, a0.x, accx); accy = fmaf(v0.x, a0.y, accy);
            accx = fmaf(v0.y, a1.x, accx); accy = fmaf(v0.y, a1.y, accy);
            accx = fmaf(v0.z, a2.x, accx); accy = fmaf(v0.z, a2.y, accy);
            accx = fmaf(v0.w, a3.x, accx); accy = fmaf(v0.w, a3.y, accy);
            accx = fmaf(v1.x, a4.x, accx); accy = fmaf(v1.x, a4.y, accy);
            accx = fmaf(v1.y, a5.x, accx); accy = fmaf(v1.y, a5.y, accy);
            accx = fmaf(v1.z, a6.x, accx); accy = fmaf(v1.z, a6.y, accy);
            accx = fmaf(v1.w, a7.x, accx); accy = fmaf(v1.w, a7.y, accy);
        }

        // 4-edge group
        for (; k + 4 <= e; k += 4) {
            float4 v0 = *reinterpret_cast<const float4*>(vals + k);
            int4   c0 = *reinterpret_cast<const int4*>(cols + k);
            float2 a0 = x2[c0.x * 32 + lane];
            float2 a1 = x2[c0.y * 32 + lane];
            float2 a2 = x2[c0.z * 32 + lane];
            float2 a3 = x2[c0.w * 32 + lane];
            accx = fmaf(v0.x, a0.x, accx); accy = fmaf(v0.x, a0.y, accy);
            accx = fmaf(v0.y, a1.x, accx); accy = fmaf(v0.y, a1.y, accy);
            accx = fmaf(v0.z, a2.x, accx); accy = fmaf(v0.z, a2.y, accy);
            accx = fmaf(v0.w, a3.x, accx); accy = fmaf(v0.w, a3.y, accy);
        }

        // Scalar tail
        for (; k < e; k++) {
            float v = vals[k];
            int   c = cols[k];
            float2 a = x2[c * 32 + lane];
            accx = fmaf(v, a.x, accx); accy = fmaf(v, a.y, accy);
        }

        if (has_bias) {
            float b = bias[row];
            accx += b; accy += b;
        }
        float2 r; r.x = accx; r.y = accy;
        reinterpret_cast<float2*>(out)[row * 32 + lane] = r;
    }
}

// ---------------------------------------------------------------------------
// Persistent fused kernel: row_ptr build + 6 SpMM phases with grid barriers.
// Removes 6 kernel-launch boundaries + per-launch overhead from the critical
// path (fp32 SpMM itself is at the measured L2/LTS roofline; the remaining
// recoverable time is inter-kernel overhead).
// ---------------------------------------------------------------------------
__global__ void __launch_bounds__(256, 8)
connectome_fused_kernel(const float* __restrict__ x,
                        const float* __restrict__ adj_vals,
                        const float* __restrict__ w_vals,
                        const float* __restrict__ bias,
                        const int* __restrict__ rows,
                        const int* __restrict__ cols,
                        float* __restrict__ out,
                        float* __restrict__ bufX,
                        float* __restrict__ bufY,
                        int* __restrict__ row_ptr,
                        int n, int nnz, int nblocks) {
    const int tid    = blockIdx.x * blockDim.x + threadIdx.x;
    const int nThr   = gridDim.x * blockDim.x;
    const int lane   = threadIdx.x & 31;
    const int warpId = tid >> 5;
    const int nWarps = nThr >> 5;

    // Snapshot the barrier generation before any barrier can be released
    // (gen only advances once ALL blocks arrive at barrier 1, and every block
    // reads it before arriving).
    int gen0 = 0;
    if (threadIdx.x == 0) gen0 = *((volatile int*)&g_bar_gen);

    // Phase 0: build CSR row_ptr from sorted rows (grid-stride over edges).
    for (int i = tid; i < nnz; i += nThr) {
        int r = rows[i];
        int rprev = (i == 0) ? -1 : rows[i - 1];
        for (int rr = rprev + 1; rr <= r; rr++) row_ptr[rr] = i;
        if (i == nnz - 1) {
            for (int rr = r + 1; rr <= n; rr++) row_ptr[rr] = nnz;
        }
    }
    grid_barrier(gen0 + 1, nblocks);

    // layer 1
    spmm_phase(w_vals,   cols, row_ptr, x,    nullptr, bufY, n, lane, warpId, nWarps, false);
    grid_barrier(gen0 + 2, nblocks);
    spmm_phase(adj_vals, cols, row_ptr, bufY, bias,    bufX, n, lane, warpId, nWarps, true);
    grid_barrier(gen0 + 3, nblocks);
    // layer 2
    spmm_phase(w_vals,   cols, row_ptr, bufX, nullptr, bufY, n, lane, warpId, nWarps, false);
    grid_barrier(gen0 + 4, nblocks);
    spmm_phase(adj_vals, cols, row_ptr, bufY, bias,    bufX, n, lane, warpId, nWarps, true);
    grid_barrier(gen0 + 5, nblocks);
    // layer 3
    spmm_phase(w_vals,   cols, row_ptr, bufX, nullptr, bufY, n, lane, warpId, nWarps, false);
    grid_barrier(gen0 + 6, nblocks);
    spmm_phase(adj_vals, cols, row_ptr, bufY, bias,    out,  n, lane, warpId, nWarps, true);
}

extern "C" void kernel_launch(void* const* d_in, const int* in_sizes, int n_in,
                              void* d_out, int out_size) {
    const float* x        = (const float*)d_in[0];   // [N, 64]
    const float* adj_vals = (const float*)d_in[1];   // [NNZ]
    const float* w_vals   = (const float*)d_in[2];   // [NNZ]
    const float* bias     = (const float*)d_in[3];   // [N]
    const int*   rows     = (const int*)d_in[4];     // [NNZ] sorted
    const int*   cols     = (const int*)d_in[5];     // [NNZ]
    // n_layers (d_in[6]) lives on device; the problem fixes it at 3.

    const int N   = in_sizes[0] / B_COLS;
    const int NNZ = in_sizes[1];

    float* bufX = nullptr; float* bufY = nullptr; int* row_ptr = nullptr;
    cudaGetSymbolAddress((void**)&bufX, g_bufX);
    cudaGetSymbolAddress((void**)&bufY, g_bufY);
    cudaGetSymbolAddress((void**)&row_ptr, g_row_ptr);

    float* outp = (float*)d_out;

    // Exactly one resident wave: 1184 blocks x 256 thr @ 32 regs
    // (2048 thr/SM, full RF) on >=148 SMs -> barrier is deadlock-free.
    const int threads = 256;
    const int blocks  = 1184;

    connectome_fused_kernel<<<blocks, threads>>>(
        x, adj_vals, w_vals, bias, rows, cols, outp,
        bufX, bufY, row_ptr, N, NNZ, blocks);
}

// round 15
// speedup vs baseline: 1.4632x; 1.4632x over previous
#include <cuda_runtime.h>

// Problem constants (fixed by the dataset)
#define B_COLS   64            // dense columns
#define N_MAX    50048         // neuron count (50000) rounded up a bit
#define NNZ_MAX  800000

// Scratch (no allocation allowed): ping-pong buffers + CSR row pointer
__device__ float g_bufX[N_MAX * B_COLS];
__device__ float g_bufY[N_MAX * B_COLS];
__device__ int   g_row_ptr[N_MAX + 1];

// ---------------------------------------------------------------------------
// Build CSR row_ptr from the sorted `rows` array.
// ---------------------------------------------------------------------------
__global__ void build_row_ptr_kernel(const int* __restrict__ rows, int nnz, int n,
                                     int* __restrict__ row_ptr) {
    int i = blockIdx.x * blockDim.x + threadIdx.x;
    if (i < nnz) {
        int r = rows[i];
        int rprev = (i == 0) ? -1 : rows[i - 1];
        for (int rr = rprev + 1; rr <= r; rr++) row_ptr[rr] = i;
        if (i == nnz - 1) {
            for (int rr = r + 1; rr <= n; rr++) row_ptr[rr] = nnz;
        }
    }
    cudaTriggerProgrammaticLaunchCompletion();
}

// ---------------------------------------------------------------------------
// CSR SpMM: out[r, :] = sum_e vals[e] * x[cols[e], :]  (+ bias[r] if HAS_BIAS)
// One warp per row (grid-stride), lane l owns dense cols {2l,2l+1} as float2.
// EXACTLY the proven R7 body (best warm config, at the measured L2/LTS
// roofline): 32-reg cap, one resident wave, vectorized uniform metadata,
// 8 independent 256B gathers in flight.
//
// PDL: prologue (IDs only) runs before cudaGridDependencySynchronize(), so a
// secondary kernel's blocks set up while the primary's stragglers finish;
// all reads of predecessor-written data (row_ptr, xin) happen after the sync.
// ---------------------------------------------------------------------------
template <bool HAS_BIAS>
__global__ void __launch_bounds__(256, 8)
spmm_kernel(const float* __restrict__ vals, const int* __restrict__ cols,
            const int* __restrict__ row_ptr, const float* __restrict__ xin,
            const float* __restrict__ bias, float* __restrict__ out, int n) {
    const int lane   = threadIdx.x & 31;
    const int warpId = (blockIdx.x * blockDim.x + threadIdx.x) >> 5;
    const int nWarps = (gridDim.x * blockDim.x) >> 5;

    // Wait for predecessor kernel's writes (row_ptr / xin) to be visible.
    cudaGridDependencySynchronize();

    const float2* __restrict__ x2 = reinterpret_cast<const float2*>(xin);

    for (int row = warpId; row < n; row += nWarps) {
        int s = row_ptr[row];
        int e = row_ptr[row + 1];

        float accx = 0.0f, accy = 0.0f;

        int k = s;
        // Peel to 4-edge alignment so float4/int4 metadata loads are 16B aligned.
        while (k < e && (k & 3)) {
            float v = vals[k];
            int   c = cols[k];
            float2 a = x2[c * 32 + lane];
            accx = fmaf(v, a.x, accx); accy = fmaf(v, a.y, accy);
            k++;
        }

        // Main body: 8 edges/iter — 2 float4 + 2 int4 uniform metadata loads,
        // 8 independent float2 gathers in flight.
        for (; k + 8 <= e; k += 8) {
            float4 v0 = *reinterpret_cast<const float4*>(vals + k);
            float4 v1 = *reinterpret_cast<const float4*>(vals + k + 4);
            int4   c0 = *reinterpret_cast<const int4*>(cols + k);
            int4   c1 = *reinterpret_cast<const int4*>(cols + k + 4);
            float2 a0 = x2[c0.x * 32 + lane];
            float2 a1 = x2[c0.y * 32 + lane];
            float2 a2 = x2[c0.z * 32 + lane];
            float2 a3 = x2[c0.w * 32 + lane];
            float2 a4 = x2[c1.x * 32 + lane];
            float2 a5 = x2[c1.y * 32 + lane];
            float2 a6 = x2[c1.z * 32 + lane];
            float2 a7 = x2[c1.w * 32 + lane];
            accx = fmaf(v0.x, a0.x, accx); accy = fmaf(v0.x, a0.y, accy);
            accx = fmaf(v0.y, a1.x, accx); accy = fmaf(v0.y, a1.y, accy);
            accx = fmaf(v0.z, a2.x, accx); accy = fmaf(v0.z, a2.y, accy);
            accx = fmaf(v0.w, a3.x, accx); accy = fmaf(v0.w, a3.y, accy);
            accx = fmaf(v1.x, a4.x, accx); accy = fmaf(v1.x, a4.y, accy);
            accx = fmaf(v1.y, a5.x, accx); accy = fmaf(v1.y, a5.y, accy);
            accx = fmaf(v1.z, a6.x, accx); accy = fmaf(v1.z, a6.y, accy);
            accx = fmaf(v1.w, a7.x, accx); accy = fmaf(v1.w, a7.y, accy);
        }

        // 4-edge group
        for (; k + 4 <= e; k += 4) {
            float4 v0 = *reinterpret_cast<const float4*>(vals + k);
            int4   c0 = *reinterpret_cast<const int4*>(cols + k);
            float2 a0 = x2[c0.x * 32 + lane];
            float2 a1 = x2[c0.y * 32 + lane];
            float2 a2 = x2[c0.z * 32 + lane];
            float2 a3 = x2[c0.w * 32 + lane];
            accx = fmaf(v0.x, a0.x, accx); accy = fmaf(v0.x, a0.y, accy);
            accx = fmaf(v0.y, a1.x, accx); accy = fmaf(v0.y, a1.y, accy);
            accx = fmaf(v0.z, a2.x, accx); accy = fmaf(v0.z, a2.y, accy);
            accx = fmaf(v0.w, a3.x, accx); accy = fmaf(v0.w, a3.y, accy);
        }

        // Scalar tail
        for (; k < e; k++) {
            float v = vals[k];
            int   c = cols[k];
            float2 a = x2[c * 32 + lane];
            accx = fmaf(v, a.x, accx); accy = fmaf(v, a.y, accy);
        }

        if (HAS_BIAS) {
            float b = bias[row];
            accx += b; accy += b;
        }
        float2 r; r.x = accx; r.y = accy;
        reinterpret_cast<float2*>(out)[row * 32 + lane] = r;
    }

    // All this block's stores are done: allow the dependent kernel to launch.
    cudaTriggerProgrammaticLaunchCompletion();
}

// Host-side helper: launch a kernel with PDL (programmatic stream
// serialization) on the default (capture) stream.
template <typename... Args>
static void launch_pdl(void (*kern)(Args...), dim3 grid, dim3 block, Args... args) {
    cudaLaunchConfig_t cfg = {};
    cfg.gridDim  = grid;
    cfg.blockDim = block;
    cfg.dynamicSmemBytes = 0;
    cfg.stream = 0;   // default stream (the one being captured)
    cudaLaunchAttribute attr[1];
    attr[0].id = cudaLaunchAttributeProgrammaticStreamSerialization;
    attr[0].val.programmaticStreamSerializationAllowed = 1;
    cfg.attrs = attr;
    cfg.numAttrs = 1;
    cudaLaunchKernelEx(&cfg, kern, args...);
}

extern "C" void kernel_launch(void* const* d_in, const int* in_sizes, int n_in,
                              void* d_out, int out_size) {
    const float* x        = (const float*)d_in[0];   // [N, 64]
    const float* adj_vals = (const float*)d_in[1];   // [NNZ]
    const float* w_vals   = (const float*)d_in[2];   // [NNZ]
    const float* bias     = (const float*)d_in[3];   // [N]
    const int*   rows     = (const int*)d_in[4];     // [NNZ] sorted
    const int*   cols     = (const int*)d_in[5];     // [NNZ]
    // n_layers (d_in[6]) lives on device; the problem fixes it at 3.

    const int N   = in_sizes[0] / B_COLS;
    const int NNZ = in_sizes[1];

    float* bufX = nullptr; float* bufY = nullptr; int* row_ptr = nullptr;
    cudaGetSymbolAddress((void**)&bufX, g_bufX);
    cudaGetSymbolAddress((void**)&bufY, g_bufY);
    cudaGetSymbolAddress((void**)&row_ptr, g_row_ptr);

    float* outp = (float*)d_out;

    // 1) row_ptr (plain launch; it is the primary of the first PDL pair)
    {
        int threads = 256;
        int blocks = (NNZ + threads - 1) / threads;
        build_row_ptr_kernel<<<blocks, threads>>>(rows, NNZ, N, row_ptr);
    }

    // 2) three layers, two SpMMs each; last write goes to d_out.
    // One resident wave: 148 SMs x 8 blocks of 256 thr (32 regs cap).
    const dim3 grid(1184), block(256);

    // layer 1
    launch_pdl(spmm_kernel<false>, grid, block, w_vals,   cols, (const int*)row_ptr, x,                   (const float*)nullptr, bufY, N);
    launch_pdl(spmm_kernel<true >, grid, block, adj_vals, cols, (const int*)row_ptr, (const float*)bufY,  bias,                  bufX, N);
    // layer 2
    launch_pdl(spmm_kernel<false>, grid, block, w_vals,   cols, (const int*)row_ptr, (const float*)bufX,  (const float*)nullptr, bufY, N);
    launch_pdl(spmm_kernel<true >, grid, block, adj_vals, cols, (const int*)row_ptr, (const float*)bufY,  bias,                  bufX, N);
    // layer 3
    launch_pdl(spmm_kernel<false>, grid, block, w_vals,   cols, (const int*)row_ptr, (const float*)bufX,  (const float*)nullptr, bufY, N);
    launch_pdl(spmm_kernel<true >, grid, block, adj_vals, cols, (const int*)row_ptr, (const float*)bufY,  bias,                  outp, N);
}

// round 17
// speedup vs baseline: 1.6114x; 1.1013x over previous
#include <cuda_runtime.h>
#include <cuda_bf16.h>

// Problem constants (fixed by the dataset)
#define B_COLS    64           // dense columns
#define N_MAX     50048        // neuron count (50000) rounded up
#define NNZ_MAX   800000
// Padded edge capacity: roundup8(NNZ) + 8*N
#define PAD_MAX   (NNZ_MAX + 8 * N_MAX + 64)

// Scratch (no allocation allowed)
// bf16x2-packed ping-pong dense buffers (lane l of a row holds cols {2l,2l+1})
__device__ unsigned int g_bA[N_MAX * 32];
__device__ unsigned int g_bB[N_MAX * 32];
__device__ int          g_row_ptr[N_MAX + 1];
__device__ float        g_wp[PAD_MAX];   // padded w_vals   (fp32)
__device__ float        g_ap[PAD_MAX];   // padded adj_vals (fp32)
__device__ int          g_cp[PAD_MAX];   // padded cols, premultiplied by 32

// ---------------------------------------------------------------------------
// Build CSR row_ptr from the sorted `rows` array.
// ---------------------------------------------------------------------------
__global__ void build_row_ptr_kernel(const int* __restrict__ rows, int nnz, int n,
                                     int* __restrict__ row_ptr) {
    int i = blockIdx.x * blockDim.x + threadIdx.x;
    if (i >= nnz) return;
    int r = rows[i];
    int rprev = (i == 0) ? -1 : rows[i - 1];
    for (int rr = rprev + 1; rr <= r; rr++) row_ptr[rr] = i;
    if (i == nnz - 1) {
        for (int rr = r + 1; rr <= n; rr++) row_ptr[rr] = nnz;
    }
}

// ---------------------------------------------------------------------------
// bf16x2 pack/unpack helpers.
// Pack: one CVT (cold path only). Unpack: SHF + LOP3, both fixed rt=2 alu ops
// — this is the whole point vs fp16, whose F2F sits on the slow ~20cyc
// convert pipe and serialized the hot loop (~11us/SpMM of F2F time).
// ---------------------------------------------------------------------------
__device__ __forceinline__ unsigned int pack_bf16x2(float x, float y) {
    __nv_bfloat162 h = __floats2bfloat162_rn(x, y);   // .x -> low 16, .y -> high 16
    return *reinterpret_cast<unsigned int*>(&h);
}
__device__ __forceinline__ float bf_lo(unsigned int b) {
    return __uint_as_float(b << 16);
}
__device__ __forceinline__ float bf_hi(unsigned int b) {
    return __uint_as_float(b & 0xFFFF0000u);
}

// ---------------------------------------------------------------------------
// fp32 [N,64] -> bf16x2 buffer (pairwise).
// ---------------------------------------------------------------------------
__global__ void f2b_kernel(const float* __restrict__ in,
                           unsigned int* __restrict__ out, int n2) {
    int i = blockIdx.x * blockDim.x + threadIdx.x;
    if (i < n2) {
        float2 f = reinterpret_cast<const float2*>(in)[i];
        out[i] = pack_bf16x2(f.x, f.y);
    }
}

// ---------------------------------------------------------------------------
// Scatter edges into the padded 8-aligned layout.
// pstart(r) = roundup8(row_ptr[r]) + 8*r (8-aligned; capacity >= roundup8(len)).
// The LAST edge of each row zero-fills its row's <=7 padding slots.
// Padding slots: val=0, col=0 -> contribute exactly 0.
// ---------------------------------------------------------------------------
__global__ void pack_kernel(const float* __restrict__ w_vals,
                            const float* __restrict__ adj_vals,
                            const int* __restrict__ rows,
                            const int* __restrict__ cols,
                            const int* __restrict__ row_ptr,
                            float* __restrict__ wp, float* __restrict__ ap,
                            int* __restrict__ cp, int nnz) {
    int i = blockIdx.x * blockDim.x + threadIdx.x;
    if (i >= nnz) return;
    int r = rows[i];
    int s = row_ptr[r];
    int base = ((s + 7) & ~7) + 8 * r;
    int dst = base + (i - s);
    wp[dst] = w_vals[i];
    ap[dst] = adj_vals[i];
    cp[dst] = cols[i] * 32;          // bf16x2 index premultiplied
    bool last = (i == nnz - 1) || (rows[i + 1] != r);
    if (last) {
        int len  = i + 1 - s;
        int pend = base + ((len + 7) & ~7);
        for (int d = dst + 1; d < pend; d++) { wp[d] = 0.0f; ap[d] = 0.0f; cp[d] = 0; }
    }
}

// ---------------------------------------------------------------------------
// Padded bf16-gather CSR SpMM:
//   out[r,:] = sum_e vals[e] * x[cols[e],:]  (+ bias[r])
// One warp per row (grid-stride). Lane l owns dense cols {2l,2l+1} as one
// packed bf16x2 (4B): gather = single 128B single-wavefront LDG.32 per edge.
// Unpack = SHF + LOP3 (cheap alu). fp32 vals, fp32 accumulation.
// Padded layout -> body is ONLY the 8-edge vectorized loop.
// Intermediates stored bf16x2; the final SpMM writes fp32 to d_out.
// ---------------------------------------------------------------------------
template <bool HAS_BIAS, bool OUT_FP32>
__global__ void __launch_bounds__(256, 8)
spmm_bf_kernel(const float* __restrict__ vals, const int* __restrict__ colsx32,
               const int* __restrict__ row_ptr,
               const unsigned int* __restrict__ xin,
               const float* __restrict__ bias, void* __restrict__ out, int n) {
    const int lane   = threadIdx.x & 31;
    const int warpId = (blockIdx.x * blockDim.x + threadIdx.x) >> 5;
    const int nWarps = (gridDim.x * blockDim.x) >> 5;

    const unsigned int* __restrict__ xl = xin + lane;   // lane-offset base

    for (int row = warpId; row < n; row += nWarps) {
        int s0 = row_ptr[row];
        int e0 = row_ptr[row + 1];
        int k  = ((s0 + 7) & ~7) + 8 * row;          // padded, 8-aligned start
        int e  = k + ((e0 - s0 + 7) & ~7);           // padded end (multiple of 8)

        float accx = 0.0f, accy = 0.0f;

        for (; k < e; k += 8) {
            float4 v0 = *reinterpret_cast<const float4*>(vals + k);
            float4 v1 = *reinterpret_cast<const float4*>(vals + k + 4);
            int4   c0 = *reinterpret_cast<const int4*>(colsx32 + k);
            int4   c1 = *reinterpret_cast<const int4*>(colsx32 + k + 4);
            unsigned int b0 = xl[c0.x];
            unsigned int b1 = xl[c0.y];
            unsigned int b2 = xl[c0.z];
            unsigned int b3 = xl[c0.w];
            unsigned int b4 = xl[c1.x];
            unsigned int b5 = xl[c1.y];
            unsigned int b6 = xl[c1.z];
            unsigned int b7 = xl[c1.w];
            accx = fmaf(v0.x, bf_lo(b0), accx); accy = fmaf(v0.x, bf_hi(b0), accy);
            accx = fmaf(v0.y, bf_lo(b1), accx); accy = fmaf(v0.y, bf_hi(b1), accy);
            accx = fmaf(v0.z, bf_lo(b2), accx); accy = fmaf(v0.z, bf_hi(b2), accy);
            accx = fmaf(v0.w, bf_lo(b3), accx); accy = fmaf(v0.w, bf_hi(b3), accy);
            accx = fmaf(v1.x, bf_lo(b4), accx); accy = fmaf(v1.x, bf_hi(b4), accy);
            accx = fmaf(v1.y, bf_lo(b5), accx); accy = fmaf(v1.y, bf_hi(b5), accy);
            accx = fmaf(v1.z, bf_lo(b6), accx); accy = fmaf(v1.z, bf_hi(b6), accy);
            accx = fmaf(v1.w, bf_lo(b7), accx); accy = fmaf(v1.w, bf_hi(b7), accy);
        }

        if (HAS_BIAS) {
            float b = bias[row];
            accx += b; accy += b;
        }
        if (OUT_FP32) {
            float2 r; r.x = accx; r.y = accy;
            reinterpret_cast<float2*>(out)[row * 32 + lane] = r;
        } else {
            reinterpret_cast<unsigned int*>(out)[row * 32 + lane] =
                pack_bf16x2(accx, accy);
        }
    }
}

extern "C" void kernel_launch(void* const* d_in, const int* in_sizes, int n_in,
                              void* d_out, int out_size) {
    const float* x        = (const float*)d_in[0];   // [N, 64]
    const float* adj_vals = (const float*)d_in[1];   // [NNZ]
    const float* w_vals   = (const float*)d_in[2];   // [NNZ]
    const float* bias     = (const float*)d_in[3];   // [N]
    const int*   rows     = (const int*)d_in[4];     // [NNZ] sorted
    const int*   cols     = (const int*)d_in[5];     // [NNZ]
    // n_layers (d_in[6]) lives on device; the problem fixes it at 3.

    const int N   = in_sizes[0] / B_COLS;
    const int NNZ = in_sizes[1];

    unsigned int* bA = nullptr; unsigned int* bB = nullptr; int* row_ptr = nullptr;
    float* wp = nullptr; float* ap = nullptr; int* cp = nullptr;
    cudaGetSymbolAddress((void**)&bA, g_bA);
    cudaGetSymbolAddress((void**)&bB, g_bB);
    cudaGetSymbolAddress((void**)&row_ptr, g_row_ptr);
    cudaGetSymbolAddress((void**)&wp, g_wp);
    cudaGetSymbolAddress((void**)&ap, g_ap);
    cudaGetSymbolAddress((void**)&cp, g_cp);

    float* outp = (float*)d_out;

    // 1) row_ptr
    {
        int threads = 256;
        int blocks = (NNZ + threads - 1) / threads;
        build_row_ptr_kernel<<<blocks, threads>>>(rows, NNZ, N, row_ptr);
    }
    // 2) x -> bf16x2 (independent of row_ptr)
    {
        int n2 = N * 32;
        int threads = 256;
        int blocks = (n2 + threads - 1) / threads;
        f2b_kernel<<<blocks, threads>>>(x, bA, n2);
    }
    // 3) padded edge format (shared by all six SpMMs); pads filled inline.
    {
        int threads = 256;
        int blocks = (NNZ + threads - 1) / threads;
        pack_kernel<<<blocks, threads>>>(w_vals, adj_vals, rows, cols, row_ptr,
                                         wp, ap, cp, NNZ);
    }

    // 4) three layers, two SpMMs each; final SpMM writes fp32 to d_out.
    const int threads = 256;
    const int blocks  = 1184;   // one resident wave, grid-stride over rows

    // layer 1
    spmm_bf_kernel<false, false><<<blocks, threads>>>(wp, cp, row_ptr, bA, nullptr, bB, N);
    spmm_bf_kernel<true,  false><<<blocks, threads>>>(ap, cp, row_ptr, bB, bias,    bA, N);
    // layer 2
    spmm_bf_kernel<false, false><<<blocks, threads>>>(wp, cp, row_ptr, bA, nullptr, bB, N);
    spmm_bf_kernel<true,  false><<<blocks, threads>>>(ap, cp, row_ptr, bB, bias,    bA, N);
    // layer 3
    spmm_bf_kernel<false, false><<<blocks, threads>>>(wp, cp, row_ptr, bA, nullptr, bB, N);
    spmm_bf_kernel<true,  true ><<<blocks, threads>>>(ap, cp, row_ptr, bB, bias,    outp, N);
}